// round 2
// baseline (speedup 1.0000x reference)
#include <cuda_runtime.h>
#include <math.h>
#include <limits.h>

// Problem constants
#define TT 10000
#define BB 4096
#define NTH 1024
#define EPT 10            // elements per thread in scan kernel (NTH*EPT >= TT)
#define CH 32             // t-steps per chunk in kill kernel

#define LOG_GAMMA_C ( 0.019802627296179713f)   // ln(1.02)
#define ALPHA_C     (-1.0050335853501451e-05f) // ln(0.99)/1000
#define INIT_LOGW_C (-1.3943265327605025f)     // ln(0.248)
#define INIT_LOGP_C (-6.907755278982137f)      // ln(0.001)
#define INV_TEMP_C  (0.001f)
#define EPSF        (1e-12f)

// Scratch (no allocations allowed)
__device__ float g_thr[TT];      // per-t u2 filter threshold (kill impossible if u2 <= thr)
__device__ float g_logit[TT];    // per-t logit
__device__ float g_pref[TT + 1]; // exclusive prefix of W_t = exp(logw_{t+1}/TEMP)
__device__ int   g_tactive;      // first t beyond which kill is impossible
__device__ int   g_tkill[BB];    // per-lane first kill step (TT = never)

// ---------------------------------------------------------------------------
// Block-wide exclusive scan (adds only — safe with -inf values)
// ---------------------------------------------------------------------------
__device__ __forceinline__ float block_exscan(float v) {
    __shared__ float sh[NTH];
    const int tid = threadIdx.x;
    sh[tid] = v;
    __syncthreads();
#pragma unroll
    for (int off = 1; off < NTH; off <<= 1) {
        float t = 0.0f;
        if (tid >= off) t = sh[tid - off];
        __syncthreads();
        if (tid >= off) sh[tid] += t;
        __syncthreads();
    }
    float ex = (tid == 0) ? 0.0f : sh[tid - 1];
    __syncthreads();
    return ex;
}

// ---------------------------------------------------------------------------
// Kernel 1: scalar recurrences via chained prefix sums (single block)
//   logw_{t+1} = logw_t + c_t,    c_t = LOG_GAMMA + log1p(-exp(a_t))
//   logp_{t+1} = logp_t + d_t,    d_t = ALPHA * exp(a_t) * exp(logw_t)
//   kill test at step t uses logp_t (pre-update); reward uses logw_{t+1}
// ---------------------------------------------------------------------------
__global__ void scan_kernel(const float* __restrict__ acts) {
    const int tid  = threadIdx.x;
    const int base = tid * EPT;
    const bool act = (base < TT);

    float f[EPT], c[EPT], w[EPT], d[EPT];
    float csum = 0.0f;
    if (act) {
#pragma unroll
        for (int i = 0; i < EPT; ++i) {
            float a = acts[base + i];
            f[i] = __expf(a);
            c[i] = LOG_GAMMA_C + log1pf(-f[i]);
            csum += c[i];
        }
    }
    float coff = block_exscan(csum);

    float lw = INIT_LOGW_C + coff;   // logw_t for first local element
    float dsum = 0.0f;
    if (act) {
#pragma unroll
        for (int i = 0; i < EPT; ++i) {
            d[i] = ALPHA_C * f[i] * __expf(lw);   // uses OLD logw (matches ref)
            lw += c[i];                            // -> logw_{t+1}
            w[i] = __expf(lw * INV_TEMP_C);        // reward weight W_t
            dsum += d[i];
        }
    }
    float doff = block_exscan(act ? dsum : 0.0f);

    float lp = INIT_LOGP_C + doff;   // logp_t for first local element
    int poss = -1;
    if (act) {
#pragma unroll
        for (int i = 0; i < EPT; ++i) {
            float e     = __expf(lp);
            float logit = lp - log1pf(-e);
            g_logit[base + i] = logit;
            float r = __expf(logit);
            // Necessary condition for kill: u2 + eps > exp(-27.631*r).
            // Use 28.0 and -1e-5 as safety margin vs reference fp32 rounding.
            g_thr[base + i] = __expf(-28.0f * r) - 1e-5f;
            // noise <= 19.95 always, so logit < -20.5 => kill impossible
            if (logit > -20.5f) poss = base + i;
            lp += d[i];
        }
    }

    float wsum = 0.0f;
    if (act) {
#pragma unroll
        for (int i = 0; i < EPT; ++i) wsum += w[i];
    }
    float woff = block_exscan(wsum);
    if (act) {
        float pw = woff;
#pragma unroll
        for (int i = 0; i < EPT; ++i) { g_pref[base + i] = pw; pw += w[i]; }
        if (base + EPT == TT) g_pref[TT] = pw;
    }

    // T_active = 1 + max t where kill possible
    __shared__ int sh_ta;
    if (tid == 0) sh_ta = 0;
    __syncthreads();
    if (poss >= 0) atomicMax(&sh_ta, poss + 1);
    __syncthreads();
    if (tid == 0) g_tactive = sh_ta;

    // reset per-lane kill step every launch (graph replays)
    for (int b = tid; b < BB; b += NTH) g_tkill[b] = TT;
}

// ---------------------------------------------------------------------------
// Kernel 2: find first kill per lane. Grid: (BB/512, ceil(TT/CH)).
// Each thread owns 4 consecutive lanes (float4 u2 loads). Blocks beyond
// T_active return immediately (skipping ~89% of input reads).
// ---------------------------------------------------------------------------
__device__ __forceinline__ bool slow_cond(float logit, float u1v, float u2v) {
    // exact reference condition: sigmoid(logit + noise) > 0.5  <=>  logit+noise > 0
    float l1    = logf(u1v + EPSF);
    float l2    = logf(u2v + EPSF);
    float noise = -logf(l2 / l1 + EPSF);
    return (logit + noise) > 0.0f;
}

__global__ void __launch_bounds__(128) kill_kernel(const float* __restrict__ u1,
                                                   const float* __restrict__ u2) {
    const int t0 = blockIdx.y * CH;
    const int ta = g_tactive;
    if (t0 >= ta) return;
    const int tend = min(t0 + CH, ta);

    __shared__ float s_thr[CH], s_lg[CH];
    if (threadIdx.x < CH) {
        int tt = t0 + threadIdx.x;
        s_thr[threadIdx.x] = (tt < TT) ? g_thr[tt]   : 2.0f;
        s_lg[threadIdx.x]  = (tt < TT) ? g_logit[tt] : -1e30f;
    }
    __syncthreads();

    const int q = blockIdx.x * blockDim.x + threadIdx.x; // quad index
    const int b = q << 2;
    const float4* p2 = (const float4*)(u2) + (size_t)t0 * (BB / 4) + q;

    int k0 = INT_MAX, k1 = INT_MAX, k2 = INT_MAX, k3 = INT_MAX;

#define PROC(v, tt)                                                                        \
    do {                                                                                   \
        float thr = s_thr[(tt) - t0];                                                      \
        if ((v).x > thr || (v).y > thr || (v).z > thr || (v).w > thr) {                    \
            float lg = s_lg[(tt) - t0];                                                    \
            size_t row = (size_t)(tt) * BB + b;                                            \
            if (k0 == INT_MAX && (v).x > thr && slow_cond(lg, u1[row + 0], (v).x)) k0 = (tt); \
            if (k1 == INT_MAX && (v).y > thr && slow_cond(lg, u1[row + 1], (v).y)) k1 = (tt); \
            if (k2 == INT_MAX && (v).z > thr && slow_cond(lg, u1[row + 2], (v).z)) k2 = (tt); \
            if (k3 == INT_MAX && (v).w > thr && slow_cond(lg, u1[row + 3], (v).w)) k3 = (tt); \
        }                                                                                  \
    } while (0)

    int t = t0;
    const int n4 = (tend - t0) >> 2;
    for (int blk = 0; blk < n4; ++blk) {
        // batch 4 row loads for MLP
        float4 v0 = p2[0 * (BB / 4)];
        float4 v1 = p2[1 * (BB / 4)];
        float4 v2 = p2[2 * (BB / 4)];
        float4 v3 = p2[3 * (BB / 4)];
        PROC(v0, t + 0);
        PROC(v1, t + 1);
        PROC(v2, t + 2);
        PROC(v3, t + 3);
        p2 += 4 * (BB / 4);
        t += 4;
    }
    for (; t < tend; ++t) {
        float4 v = *p2;
        PROC(v, t);
        p2 += BB / 4;
    }
#undef PROC

    if (k0 != INT_MAX) atomicMin(&g_tkill[b + 0], k0);
    if (k1 != INT_MAX) atomicMin(&g_tkill[b + 1], k1);
    if (k2 != INT_MAX) atomicMin(&g_tkill[b + 2], k2);
    if (k3 != INT_MAX) atomicMin(&g_tkill[b + 3], k3);
}

// ---------------------------------------------------------------------------
// Kernel 3: mean over batch of Pref[t_kill]
// ---------------------------------------------------------------------------
__global__ void reduce_kernel(float* __restrict__ out) {
    __shared__ double sh[256];
    const int tid = threadIdx.x;
    double s = 0.0;
    for (int b = tid; b < BB; b += 256) s += (double)g_pref[g_tkill[b]];
    sh[tid] = s;
    __syncthreads();
    for (int off = 128; off > 0; off >>= 1) {
        if (tid < off) sh[tid] += sh[tid + off];
        __syncthreads();
    }
    if (tid == 0) out[0] = (float)(sh[0] / (double)BB);
}

// ---------------------------------------------------------------------------
extern "C" void kernel_launch(void* const* d_in, const int* in_sizes, int n_in,
                              void* d_out, int out_size) {
    const float* acts = (const float*)d_in[0];
    const float* u1   = (const float*)d_in[1];
    const float* u2   = (const float*)d_in[2];

    scan_kernel<<<1, NTH>>>(acts);

    dim3 grid(BB / (128 * 4), (TT + CH - 1) / CH);
    kill_kernel<<<grid, 128>>>(u1, u2);

    reduce_kernel<<<1, 256>>>((float*)d_out);
}

// round 3
// speedup vs baseline: 1.6843x; 1.6843x over previous
#include <cuda_runtime.h>
#include <math.h>
#include <limits.h>

// Problem constants
#define TT 10000
#define BB 4096
#define NTH 1024
#define EPT 10            // elements per thread in scan kernel (NTH*EPT >= TT)
#define CH 8              // t-steps per chunk in kill kernel
#define KGY 160           // kill grid y

#define LOG_GAMMA_C ( 0.019802627296179713f)   // ln(1.02)
#define ALPHA_C     (-1.0050335853501451e-05f) // ln(0.99)/1000
#define INIT_LOGW_C (-1.3943265327605025f)     // ln(0.248)
#define INIT_LOGP_C (-6.907755278982137f)      // ln(0.001)
#define INV_TEMP_C  (0.001f)
#define EPSF        (1e-12f)

// Scratch (no allocations allowed)
__device__ float g_f[TT];        // exp(a_t)
__device__ float g_c[TT];        // LOG_GAMMA + log(1 - f_t)
__device__ float g_lp[TT];       // logp_t (pre-update, used in kill test at step t)
__device__ float g_thr[TT];      // per-t u2 filter threshold (kill impossible if u2 <= thr)
__device__ float g_logit[TT];    // per-t logit
__device__ float g_pref[TT + 1]; // exclusive prefix of W_t = exp(logw_{t+1}/TEMP)
__device__ int   g_tactive;      // first t beyond which kill is impossible
__device__ int   g_tkill[BB];    // per-lane first kill step (TT = never)

// ---------------------------------------------------------------------------
// K0: elementwise pre-pass (multi-block). Also resets g_tactive / g_tkill.
// ---------------------------------------------------------------------------
__global__ void pre_kernel(const float* __restrict__ acts) {
    int i = blockIdx.x * blockDim.x + threadIdx.x;
    if (i < TT) {
        float a = acts[i];
        float f = __expf(a);
        g_f[i] = f;
        g_c[i] = LOG_GAMMA_C + __logf(1.0f - f);  // reference: log(1.0 - f)
    }
    if (i < BB) g_tkill[i] = TT;
    if (i == 0) g_tactive = 0;
}

// ---------------------------------------------------------------------------
// Block-wide exclusive scan via warp shuffles (2 barriers total)
// ---------------------------------------------------------------------------
__device__ __forceinline__ float block_exscan(float v) {
    __shared__ float ws[32];
    const int lane = threadIdx.x & 31;
    const int wid  = threadIdx.x >> 5;
    float s = v;
#pragma unroll
    for (int o = 1; o < 32; o <<= 1) {
        float n = __shfl_up_sync(0xffffffffu, s, o);
        if (lane >= o) s += n;
    }
    float exw = __shfl_up_sync(0xffffffffu, s, 1);   // exclusive within warp
    if (lane == 0) exw = 0.0f;
    if (lane == 31) ws[wid] = s;                      // warp totals
    __syncthreads();
    if (wid == 0) {
        float t = ws[lane];
#pragma unroll
        for (int o = 1; o < 32; o <<= 1) {
            float n = __shfl_up_sync(0xffffffffu, t, o);
            if (lane >= o) t += n;
        }
        float exb = __shfl_up_sync(0xffffffffu, t, 1);
        if (lane == 0) exb = 0.0f;
        ws[lane] = exb;
    }
    __syncthreads();
    return ws[wid] + exw;
}

// ---------------------------------------------------------------------------
// K1: the three chained prefix sums (single block, scan-only work)
//   logw_{t+1} = logw_t + c_t
//   logp_{t+1} = logp_t + d_t,  d_t = ALPHA * f_t * exp(logw_t)
//   W_t = exp(logw_{t+1} / TEMP);  pref = exclusive prefix of W
// ---------------------------------------------------------------------------
__global__ void scan_kernel() {
    const int tid  = threadIdx.x;
    const int base = tid * EPT;
    const bool act = (base < TT);

    float f[EPT], c[EPT], d[EPT], w[EPT];
    float csum = 0.0f;
    if (act) {
#pragma unroll
        for (int i = 0; i < EPT; ++i) {
            f[i] = g_f[base + i];
            c[i] = g_c[base + i];
            csum += c[i];
        }
    }
    float coff = block_exscan(act ? csum : 0.0f);

    float dsum = 0.0f, wsum = 0.0f;
    if (act) {
        float lw0 = INIT_LOGW_C + coff;          // logw at first local element
        float elw = __expf(lw0);                  // exp(logw_t), anchored per thread
        float wv  = __expf(lw0 * INV_TEMP_C);     // exp(logw_t/TEMP) anchor
        float lwl = 0.0f;                         // local c prefix
#pragma unroll
        for (int i = 0; i < EPT; ++i) {
            d[i] = ALPHA_C * f[i] * elw;          // uses OLD logw (matches ref)
            elw *= 1.02f * (1.0f - f[i]);         // exp(logw_{t+1}) = exp(logw_t)*gamma*(1-f)
            lwl += c[i];
            float x = lwl * INV_TEMP_C;           // |x| <= 2e-4: 2nd-order exp
            w[i] = wv * (1.0f + x * (1.0f + 0.5f * x));
            dsum += d[i];
            wsum += w[i];
        }
    }
    float doff = block_exscan(act ? dsum : 0.0f);
    float woff = block_exscan(act ? wsum : 0.0f);

    if (act) {
        float lp = INIT_LOGP_C + doff;
        float pw = woff;
#pragma unroll
        for (int i = 0; i < EPT; ++i) {
            g_lp[base + i]   = lp;  lp += d[i];
            g_pref[base + i] = pw;  pw += w[i];
        }
        if (base + EPT == TT) g_pref[TT] = pw;
    }
}

// ---------------------------------------------------------------------------
// K2: elementwise post-pass (multi-block): logit, filter threshold, T_active
// ---------------------------------------------------------------------------
__global__ void post_kernel() {
    int i = blockIdx.x * blockDim.x + threadIdx.x;
    if (i >= TT) return;
    float lp = g_lp[i];
    float e  = __expf(lp);
    float logit = lp - log1pf(-e);               // reference: log1p(-exp(logp))
    g_logit[i] = logit;
    float r = e / (1.0f - e);                    // = exp(logit)
    // Necessary condition for kill: u2 + eps > exp(-27.631*r).
    // Use 28.0 and -1e-5 as safety margin vs reference fp32 rounding.
    g_thr[i] = __expf(-28.0f * r) - 1e-5f;
    // noise <= 19.95 always (fp32 uniforms < 1), so logit < -20.5 => no kill
    if (logit > -20.5f) atomicMax(&g_tactive, i + 1);
}

// ---------------------------------------------------------------------------
// K3: find first kill per lane. Fixed grid (BB/512, KGY); chunk-stride in t.
// Each thread owns 4 consecutive lanes (float4 u2 loads), 8 rows batched.
// ---------------------------------------------------------------------------
__device__ __forceinline__ bool slow_cond(float logit, float u1v, float u2v) {
    // exact reference condition: sigmoid(logit + noise) > 0.5  <=>  logit+noise > 0
    float l1    = logf(u1v + EPSF);
    float l2    = logf(u2v + EPSF);
    float noise = -logf(l2 / l1 + EPSF);
    return (logit + noise) > 0.0f;
}

__global__ void __launch_bounds__(128) kill_kernel(const float* __restrict__ u1,
                                                   const float* __restrict__ u2) {
    const int ta = g_tactive;
    if (ta <= 0) return;
    const int nchunks = (ta + CH - 1) / CH;

    const int q = blockIdx.x * blockDim.x + threadIdx.x; // quad index (0..1023)
    const int b = q << 2;
    const float4* u2v = (const float4*)u2;

    int k0 = INT_MAX, k1 = INT_MAX, k2 = INT_MAX, k3 = INT_MAX;

    for (int cy = blockIdx.y; cy < nchunks; cy += KGY) {
        const int t0   = cy * CH;
        const int tend = min(t0 + CH, ta);

        // batch all CH row loads for MLP=8
        float4 v[CH];
#pragma unroll
        for (int i = 0; i < CH; ++i) {
            int tt = min(t0 + i, TT - 1);
            v[i] = u2v[(size_t)tt * (BB / 4) + q];
        }

#pragma unroll
        for (int i = 0; i < CH; ++i) {
            int tt = t0 + i;
            if (tt >= tend) break;
            float thr = __ldg(&g_thr[tt]);        // uniform address -> broadcast
            float4 vv = v[i];
            if (vv.x > thr || vv.y > thr || vv.z > thr || vv.w > thr) {
                float lg = __ldg(&g_logit[tt]);
                size_t row = (size_t)tt * BB + b;
                if (k0 == INT_MAX && vv.x > thr && slow_cond(lg, u1[row + 0], vv.x)) k0 = tt;
                if (k1 == INT_MAX && vv.y > thr && slow_cond(lg, u1[row + 1], vv.y)) k1 = tt;
                if (k2 == INT_MAX && vv.z > thr && slow_cond(lg, u1[row + 2], vv.z)) k2 = tt;
                if (k3 == INT_MAX && vv.w > thr && slow_cond(lg, u1[row + 3], vv.w)) k3 = tt;
            }
        }
    }

    if (k0 != INT_MAX) atomicMin(&g_tkill[b + 0], k0);
    if (k1 != INT_MAX) atomicMin(&g_tkill[b + 1], k1);
    if (k2 != INT_MAX) atomicMin(&g_tkill[b + 2], k2);
    if (k3 != INT_MAX) atomicMin(&g_tkill[b + 3], k3);
}

// ---------------------------------------------------------------------------
// K4: mean over batch of Pref[t_kill]
// ---------------------------------------------------------------------------
__global__ void reduce_kernel(float* __restrict__ out) {
    __shared__ double sh[256];
    const int tid = threadIdx.x;
    double s = 0.0;
    for (int b = tid; b < BB; b += 256) s += (double)g_pref[g_tkill[b]];
    sh[tid] = s;
    __syncthreads();
    for (int off = 128; off > 0; off >>= 1) {
        if (tid < off) sh[tid] += sh[tid + off];
        __syncthreads();
    }
    if (tid == 0) out[0] = (float)(sh[0] / (double)BB);
}

// ---------------------------------------------------------------------------
extern "C" void kernel_launch(void* const* d_in, const int* in_sizes, int n_in,
                              void* d_out, int out_size) {
    const float* acts = (const float*)d_in[0];
    const float* u1   = (const float*)d_in[1];
    const float* u2   = (const float*)d_in[2];

    pre_kernel<<<(TT + 511) / 512, 512>>>(acts);
    scan_kernel<<<1, NTH>>>();
    post_kernel<<<(TT + 511) / 512, 512>>>();

    dim3 grid(BB / (128 * 4), KGY);
    kill_kernel<<<grid, 128>>>(u1, u2);

    reduce_kernel<<<1, 256>>>((float*)d_out);
}

// round 4
// speedup vs baseline: 1.9909x; 1.1821x over previous
#include <cuda_runtime.h>
#include <math.h>
#include <limits.h>

// Problem constants
#define TT 10000
#define BB 4096
#define NTH 1024
#define EPT 10            // elements per thread in scan kernel (NTH*EPT >= TT)
#define CH 8              // t-steps per chunk in kill kernel
#define KGX 4             // kill grid x  (KGX*256*4 == BB lanes)
#define KGY 160           // kill grid y
#define NBLK (KGX * KGY)  // total kill blocks (all reach the ticket counter)

#define LOG_GAMMA_C ( 0.019802627296179713f)   // ln(1.02)
#define ALPHA_C     (-1.0050335853501451e-05f) // ln(0.99)/1000
#define INIT_LOGW_C (-1.3943265327605025f)     // ln(0.248)
#define INIT_LOGP_C (-6.907755278982137f)      // ln(0.001)
#define INV_TEMP_C  (0.001f)
#define EPSF        (1e-12f)

// Scratch (no allocations allowed)
__device__ float2       g_row[TT];      // per-t {thr, rm}: u2 filter threshold, r - eps
__device__ float        g_pref[TT + 1]; // exclusive prefix of W_t = exp(logw_{t+1}/TEMP)
__device__ int          g_tactive;      // first t beyond which kill is impossible
__device__ int          g_tkill[BB];    // per-lane first kill step (TT = never)
__device__ unsigned int g_done;         // kill-block completion ticket

// ---------------------------------------------------------------------------
// Block-wide exclusive scan via warp shuffles (2 barriers)
// ---------------------------------------------------------------------------
__device__ __forceinline__ float block_exscan(float v) {
    __shared__ float ws[32];
    const int lane = threadIdx.x & 31;
    const int wid  = threadIdx.x >> 5;
    float s = v;
#pragma unroll
    for (int o = 1; o < 32; o <<= 1) {
        float n = __shfl_up_sync(0xffffffffu, s, o);
        if (lane >= o) s += n;
    }
    float exw = __shfl_up_sync(0xffffffffu, s, 1);
    if (lane == 0) exw = 0.0f;
    if (lane == 31) ws[wid] = s;
    __syncthreads();
    if (wid == 0) {
        float t = ws[lane];
#pragma unroll
        for (int o = 1; o < 32; o <<= 1) {
            float n = __shfl_up_sync(0xffffffffu, t, o);
            if (lane >= o) t += n;
        }
        float exb = __shfl_up_sync(0xffffffffu, t, 1);
        if (lane == 0) exb = 0.0f;
        ws[lane] = exb;
    }
    __syncthreads();
    return ws[wid] + exw;
}

// ---------------------------------------------------------------------------
// K1 (single block): everything that depends only on acts.
//   logw_{t+1} = logw_t + c_t,  c_t = LOG_GAMMA + log(1-f_t),  f_t = exp(a_t)
//   logp_{t+1} = logp_t + d_t,  d_t = ALPHA * f_t * exp(logw_t)
//   W_t = exp(logw_{t+1}/TEMP); pref = exclusive prefix of W
//   per-t kill row data: r = exp(logit); thr = exp(-28 r) - 1e-5; rm = r - eps
//   Also resets g_tkill / g_done and computes T_active.
// ---------------------------------------------------------------------------
__global__ void __launch_bounds__(NTH) scan_kernel(const float* __restrict__ acts) {
    const int tid  = threadIdx.x;
    const int base = tid * EPT;
    const bool act = (base < TT);

    float f[EPT], c[EPT], d[EPT], w[EPT];
    float csum = 0.0f;
    if (act) {
#pragma unroll
        for (int i = 0; i < EPT; ++i) {
            float a = acts[base + i];
            f[i] = __expf(a);
            c[i] = LOG_GAMMA_C + __logf(1.0f - f[i]);
            csum += c[i];
        }
    }
    float coff = block_exscan(act ? csum : 0.0f);

    float dsum = 0.0f, wsum = 0.0f;
    if (act) {
        float lw0 = INIT_LOGW_C + coff;        // logw at first local element
        float elw = __expf(lw0);                // exp(logw_t) anchor, multiplicative recur
        float wv  = __expf(lw0 * INV_TEMP_C);   // exp(logw_t/TEMP) anchor
        float lwl = 0.0f;                       // local c prefix
#pragma unroll
        for (int i = 0; i < EPT; ++i) {
            d[i] = ALPHA_C * f[i] * elw;        // uses OLD logw (matches ref)
            elw *= 1.02f * (1.0f - f[i]);       // exp(logw_{t+1})
            lwl += c[i];
            float x = lwl * INV_TEMP_C;         // |x| <= 2e-4: 2nd-order exp
            w[i] = wv * (1.0f + x * (1.0f + 0.5f * x));
            dsum += d[i];
            wsum += w[i];
        }
    }
    float doff = block_exscan(act ? dsum : 0.0f);
    float woff = block_exscan(act ? wsum : 0.0f);

    int poss = -1;
    if (act) {
        float lp = INIT_LOGP_C + doff;
        float pw = woff;
#pragma unroll
        for (int i = 0; i < EPT; ++i) {
            g_pref[base + i] = pw;  pw += w[i];
            float e     = __expf(lp);
            float logit = lp - __logf(1.0f - e);
            float r     = e / (1.0f - e);       // exp(logit)
            // Necessary condition for kill: u2 + eps > exp(-27.631*r)
            // (|log(u1+eps)| <= 27.631). 28.0 / -1e-5 = safety margin.
            float thr = __expf(-28.0f * r) - 1e-5f;
            g_row[base + i] = make_float2(thr, r - EPSF);
            // noise <= 19.95 always, so logit < -20.5 => kill impossible
            if (logit > -20.5f) poss = base + i;
            lp += d[i];
        }
        if (base + EPT == TT) g_pref[TT] = pw;
    }

    __shared__ int sh_ta;
    if (tid == 0) sh_ta = 0;
    __syncthreads();
    if (poss >= 0) atomicMax(&sh_ta, poss + 1);
    __syncthreads();
    if (tid == 0) { g_tactive = sh_ta; g_done = 0u; }

    // reset per-lane kill step every launch (graph replays)
    for (int b = tid; b < BB; b += NTH) g_tkill[b] = TT;
}

// ---------------------------------------------------------------------------
// K2: find first kill per lane + fused final reduction (last-block pattern).
// Exact kill condition rewrite (real-math equivalent of the reference):
//   sigmoid(logit + noise) > 0.5
//   <=> L2/L1 + eps < exp(logit) = r         (L1 = log(u1+eps) < 0, L2 = log(u2+eps))
//   <=> L2 > (r - eps) * L1                  (multiply by L1 < 0 flips)
// ---------------------------------------------------------------------------
__global__ void __launch_bounds__(256) kill_kernel(const float* __restrict__ u1,
                                                   const float* __restrict__ u2,
                                                   float* __restrict__ out) {
    const int ta      = g_tactive;
    const int nchunks = (ta + CH - 1) / CH;

    const int q = blockIdx.x * 256 + threadIdx.x;  // quad index (0..1023)
    const int b = q << 2;
    const float4* __restrict__ u2v = (const float4*)u2;

    int k0 = INT_MAX, k1 = INT_MAX, k2 = INT_MAX, k3 = INT_MAX;

    for (int cy = blockIdx.y; cy < nchunks; cy += KGY) {
        const int t0 = cy * CH;

        // batch all CH row loads (MLP = 8); t0+CH-1 <= ta+6 < TT so in-bounds
        float4 v[CH];
#pragma unroll
        for (int i = 0; i < CH; ++i)
            v[i] = u2v[(t0 + i) * (BB / 4) + q];

#pragma unroll
        for (int i = 0; i < CH; ++i) {
            const int tt = t0 + i;
            if (tt >= ta) break;
            const float2 row = g_row[tt];          // {thr, rm}, uniform -> broadcast
            const float4 vv = v[i];
            const float m = fmaxf(fmaxf(vv.x, vv.y), fmaxf(vv.z, vv.w));
            if (m > row.x) {
                const int rb = tt * BB + b;        // fits in 32 bits (ta*BB < 2^31)
                const float rm = row.y;
                if (k0 == INT_MAX && vv.x > row.x) {
                    float L1 = __logf(u1[rb + 0] + EPSF), L2 = __logf(vv.x + EPSF);
                    if (L2 > rm * L1) k0 = tt;
                }
                if (k1 == INT_MAX && vv.y > row.x) {
                    float L1 = __logf(u1[rb + 1] + EPSF), L2 = __logf(vv.y + EPSF);
                    if (L2 > rm * L1) k1 = tt;
                }
                if (k2 == INT_MAX && vv.z > row.x) {
                    float L1 = __logf(u1[rb + 2] + EPSF), L2 = __logf(vv.z + EPSF);
                    if (L2 > rm * L1) k2 = tt;
                }
                if (k3 == INT_MAX && vv.w > row.x) {
                    float L1 = __logf(u1[rb + 3] + EPSF), L2 = __logf(vv.w + EPSF);
                    if (L2 > rm * L1) k3 = tt;
                }
            }
        }
    }

    if (k0 != INT_MAX) atomicMin(&g_tkill[b + 0], k0);
    if (k1 != INT_MAX) atomicMin(&g_tkill[b + 1], k1);
    if (k2 != INT_MAX) atomicMin(&g_tkill[b + 2], k2);
    if (k3 != INT_MAX) atomicMin(&g_tkill[b + 3], k3);

    // ---- fused reduction: last block to finish gathers Pref[t_kill] & means ----
    __shared__ bool is_last;
    __threadfence();
    if (threadIdx.x == 0) {
        unsigned int t = atomicAdd(&g_done, 1u);
        is_last = (t == NBLK - 1u);
    }
    __syncthreads();
    if (!is_last) return;
    __threadfence();

    __shared__ double sh[256];
    const int tid = threadIdx.x;
    double s = 0.0;
    for (int bb = tid; bb < BB; bb += 256) s += (double)g_pref[g_tkill[bb]];
    sh[tid] = s;
    __syncthreads();
#pragma unroll
    for (int off = 128; off > 0; off >>= 1) {
        if (tid < off) sh[tid] += sh[tid + off];
        __syncthreads();
    }
    if (tid == 0) out[0] = (float)(sh[0] / (double)BB);
}

// ---------------------------------------------------------------------------
extern "C" void kernel_launch(void* const* d_in, const int* in_sizes, int n_in,
                              void* d_out, int out_size) {
    const float* acts = (const float*)d_in[0];
    const float* u1   = (const float*)d_in[1];
    const float* u2   = (const float*)d_in[2];

    scan_kernel<<<1, NTH>>>(acts);

    dim3 grid(KGX, KGY);
    kill_kernel<<<grid, 256>>>(u1, u2, (float*)d_out);
}